// round 2
// baseline (speedup 1.0000x reference)
#include <cuda_runtime.h>
#include <cstdint>

#define NN   2048
#define EE   262144
#define SD   256
#define VD   64
#define ED   32
#define NMOL 64
#define NAF  16
#define NBT  5

typedef unsigned long long u64;

// ---- scratch (device globals; no allocations) ----
__device__ __align__(16) float g_sh[NN * SD];        // s_h = silu(s@Ws+bs)
__device__ __align__(16) float g_G[NN * SD];         // G = s_h @ W0[0:256,:]
__device__ __align__(16) float g_cpraw[NN * 3];      // p + v@Wc
__device__ __align__(16) float g_cp[NN * 3];         // centered coords
__device__ __align__(16) float g_molmean[NMOL * 3];
__device__ __align__(16) float g_M[ED * SD];         // M = Wb @ W0a
__device__ __align__(16) float g_c0[SD];             // c0 = b0 + bb @ W0a
__device__ int   g_map[NN * NN];                     // last-edge-index map

__device__ __forceinline__ float silu_f(float x) {
    return __fdividef(x, 1.0f + __expf(-x));
}

// ---- packed f32x2 helpers (Blackwell dual-fp32 path, PTX-only) ----
__device__ __forceinline__ u64 pack2(float a, float b) {
    u64 r; asm("mov.b64 %0, {%1, %2};" : "=l"(r) : "f"(a), "f"(b)); return r;
}
__device__ __forceinline__ void unpack2(u64 v, float& a, float& b) {
    asm("mov.b64 {%0, %1}, %2;" : "=f"(a), "=f"(b) : "l"(v));
}
__device__ __forceinline__ u64 ffma2(u64 a, u64 b, u64 c) {
    u64 d; asm("fma.rn.f32x2 %0, %1, %2, %3;" : "=l"(d) : "l"(a), "l"(b), "l"(c)); return d;
}
__device__ __forceinline__ u64 fadd2(u64 a, u64 b) {
    u64 d; asm("add.rn.f32x2 %0, %1, %2;" : "=l"(d) : "l"(a), "l"(b)); return d;
}
__device__ __forceinline__ void lds_v2u64(u64& a, u64& b, uint32_t addr) {
    asm volatile("ld.shared.v2.b64 {%0, %1}, [%2];" : "=l"(a), "=l"(b) : "r"(addr));
}

// ---- K0: clear map ----
__global__ void k_clear() {
    int i = blockIdx.x * blockDim.x + threadIdx.x;
    int stride = gridDim.x * blockDim.x;
    for (; i < NN * NN; i += stride) g_map[i] = -1;
}

// ---- K5: scatter last-edge-wins ----
__global__ void k_scatter(const int* __restrict__ eg) {
    int k = blockIdx.x * blockDim.x + threadIdx.x;
    if (k < EE) {
        int j = eg[k];
        int i = eg[EE + k];
        atomicMax(&g_map[j * NN + i], k);
    }
}

// ---- K1: s_h = silu(s@Ws+bs), cpraw = p + v@Wc ----
__global__ __launch_bounds__(256) void k_node1(
    const float* __restrict__ s, const float* __restrict__ v,
    const float* __restrict__ p, const float* __restrict__ Ws,
    const float* __restrict__ bs, const float* __restrict__ Wc)
{
    __shared__ float ss[8][SD];
    const int t = threadIdx.x;
    const int n0 = blockIdx.x * 8;
    #pragma unroll
    for (int r = 0; r < 8; r++) ss[r][t] = s[(n0 + r) * SD + t];
    __syncthreads();

    float acc[8];
    #pragma unroll
    for (int r = 0; r < 8; r++) acc[r] = 0.0f;

    for (int k = 0; k < SD; k += 4) {
        float w0 = Ws[(k + 0) * SD + t];
        float w1 = Ws[(k + 1) * SD + t];
        float w2 = Ws[(k + 2) * SD + t];
        float w3 = Ws[(k + 3) * SD + t];
        #pragma unroll
        for (int r = 0; r < 8; r++) {
            float4 a = *(const float4*)&ss[r][k];
            acc[r] += a.x * w0;
            acc[r] += a.y * w1;
            acc[r] += a.z * w2;
            acc[r] += a.w * w3;
        }
    }
    float b = bs[t];
    #pragma unroll
    for (int r = 0; r < 8; r++) {
        g_sh[(n0 + r) * SD + t] = silu_f(acc[r] + b);
    }

    if (t < 24) {
        int r = t / 3, x = t % 3;
        const float* vp = &v[(n0 + r) * 3 * VD + x * VD];
        float sum = 0.0f;
        #pragma unroll 8
        for (int q = 0; q < VD; q++) sum += vp[q] * Wc[q];
        g_cpraw[(n0 + r) * 3 + x] = p[(n0 + r) * 3 + x] + sum;
    }
}

// ---- K2: M = Wb@W0a (blocks 0..31), c0 = b0 + bb@W0a (block 32); split-K x4 ----
__global__ __launch_bounds__(1024) void k_mw(
    const float* __restrict__ Wb, const float* __restrict__ bb,
    const float* __restrict__ W0, const float* __restrict__ b0)
{
    __shared__ float row[SD];
    __shared__ float part[3][SD];
    const int t = threadIdx.x;
    const int c = t & 255;
    const int pz = t >> 8;              // 0..3 split-K group
    const int q = blockIdx.x;
    if (t < SD) row[t] = (q < ED) ? Wb[q * SD + t] : bb[t];
    __syncthreads();

    float acc = 0.0f;
    const int k0 = pz * 64;
    #pragma unroll 4
    for (int k = k0; k < k0 + 64; k += 4) {
        float4 a = *(const float4*)&row[k];
        acc += a.x * W0[(k + 0) * SD + c];
        acc += a.y * W0[(k + 1) * SD + c];
        acc += a.z * W0[(k + 2) * SD + c];
        acc += a.w * W0[(k + 3) * SD + c];
    }
    if (pz > 0) part[pz - 1][c] = acc;
    __syncthreads();
    if (pz == 0) {
        float tot = acc + part[0][c] + part[1][c] + part[2][c];
        if (q < ED) g_M[q * SD + c] = tot;
        else        g_c0[c] = b0[c] + tot;
    }
}

// ---- K3a: per-mol mean ----
__global__ void k_molmean(const int* __restrict__ batch) {
    __shared__ float red[128][4];
    const int b = blockIdx.x;
    const int t = threadIdx.x;
    float sx = 0.f, sy = 0.f, sz = 0.f, c = 0.f;
    for (int n = t; n < NN; n += 128) {
        if (batch[n] == b) {
            sx += g_cpraw[n * 3 + 0];
            sy += g_cpraw[n * 3 + 1];
            sz += g_cpraw[n * 3 + 2];
            c  += 1.0f;
        }
    }
    red[t][0] = sx; red[t][1] = sy; red[t][2] = sz; red[t][3] = c;
    __syncthreads();
    for (int s = 64; s > 0; s >>= 1) {
        if (t < s) {
            red[t][0] += red[t + s][0];
            red[t][1] += red[t + s][1];
            red[t][2] += red[t + s][2];
            red[t][3] += red[t + s][3];
        }
        __syncthreads();
    }
    if (t < 3) g_molmean[b * 3 + t] = red[0][t] / fmaxf(red[0][3], 1.0f);
}

// ---- K3b: center coords + write output ----
__global__ void k_center(const int* __restrict__ batch, float* __restrict__ out_coords) {
    int n = blockIdx.x * blockDim.x + threadIdx.x;
    if (n < NN) {
        int b = batch[n];
        #pragma unroll
        for (int x = 0; x < 3; x++) {
            float cpv = g_cpraw[n * 3 + x] - g_molmean[b * 3 + x];
            g_cp[n * 3 + x] = cpv;
            out_coords[n * 3 + x] = cpv;
        }
    }
}

// ---- K4: G = s_h@W0a and atoms_pred = s_h@Wa + ba ----
__global__ __launch_bounds__(256) void k_node2(
    const float* __restrict__ W0, const float* __restrict__ Wa,
    const float* __restrict__ ba, float* __restrict__ out_atoms)
{
    __shared__ float sh[8][SD];
    const int t = threadIdx.x;
    const int n0 = blockIdx.x * 8;
    #pragma unroll
    for (int r = 0; r < 8; r++) sh[r][t] = g_sh[(n0 + r) * SD + t];
    __syncthreads();

    float acc[8];
    #pragma unroll
    for (int r = 0; r < 8; r++) acc[r] = 0.0f;
    for (int k = 0; k < SD; k += 4) {
        float w0 = W0[(k + 0) * SD + t];
        float w1 = W0[(k + 1) * SD + t];
        float w2 = W0[(k + 2) * SD + t];
        float w3 = W0[(k + 3) * SD + t];
        #pragma unroll
        for (int r = 0; r < 8; r++) {
            float4 a = *(const float4*)&sh[r][k];
            acc[r] += a.x * w0;
            acc[r] += a.y * w1;
            acc[r] += a.z * w2;
            acc[r] += a.w * w3;
        }
    }
    #pragma unroll
    for (int r = 0; r < 8; r++) g_G[(n0 + r) * SD + t] = acc[r];

    if (t < 8 * NAF) {
        int r = t >> 4, a = t & 15;
        float sum = 0.0f;
        for (int k = 0; k < SD; k++) sum += sh[r][k] * Wa[k * NAF + a];
        out_atoms[(n0 + r) * NAF + a] = sum + ba[a];
    }
}

// ---- K6: fused edge kernel with packed f32x2 math ----
// z = c0 + e_sym@M + G[i] + G[j] + d*W0[256,:];  bonds = silu(z)@W1 + b1
__global__ __launch_bounds__(256, 2) void k_edge(
    const int* __restrict__ eg, const float* __restrict__ efeat,
    const float* __restrict__ W0, const float* __restrict__ W1,
    const float* __restrict__ b1, float* __restrict__ out_bonds)
{
    __shared__ float sM[ED][SD];       // 32 KB
    __shared__ float sE[64][ED + 1];   // 8.25 KB
    __shared__ int   sI[64], sJ[64], sKa[64], sKb[64];
    __shared__ float sD[64];

    const int t = threadIdx.x;
    const int base = blockIdx.x * 64;

    {   // stage M into smem
        const float4* src = (const float4*)g_M;
        float4* dst = (float4*)sM;
        #pragma unroll
        for (int r = 0; r < 8; r++) dst[t + 256 * r] = src[t + 256 * r];
    }
    if (t < 64) {
        int eid = base + t;
        int j = eg[eid], i = eg[EE + eid];
        sI[t] = i; sJ[t] = j;
        sKa[t] = g_map[j * NN + i];
        sKb[t] = g_map[i * NN + j];
        float dx = g_cp[i * 3 + 0] - g_cp[j * 3 + 0];
        float dy = g_cp[i * 3 + 1] - g_cp[j * 3 + 1];
        float dz = g_cp[i * 3 + 2] - g_cp[j * 3 + 2];
        sD[t] = dx * dx + dy * dy + dz * dz;
    }
    __syncthreads();

    // build e_sym = 0.5*(e[ka] + (kb>=0 ? e[kb] : 0))
    #pragma unroll
    for (int r = 0; r < 8; r++) {
        int idx = t + 256 * r;
        int m = idx >> 5, q = idx & 31;
        int ka = sKa[m], kb = sKb[m];
        float vv = efeat[ka * ED + q];
        if (kb >= 0) vv += efeat[kb * ED + q];
        sE[m][q] = 0.5f * vv;
    }
    __syncthreads();

    const int ng = t & 15;        // 16 column-groups of 16 hidden cols
    const int mg = t >> 4;        // 16 row-groups of 4 edges
    const int ccol = ng * 16;

    // packed accumulators: acc2[r][u] holds cols (ccol+2u, ccol+2u+1)
    u64 acc2[4][8];
    {
        const u64* c0p = (const u64*)&g_c0[ccol];
        u64 c0v[8];
        #pragma unroll
        for (int u = 0; u < 8; u++) c0v[u] = c0p[u];
        #pragma unroll
        for (int r = 0; r < 4; r++)
            #pragma unroll
            for (int u = 0; u < 8; u++) acc2[r][u] = c0v[u];
    }

    const uint32_t sMb = (uint32_t)__cvta_generic_to_shared(&sM[0][0]) + ccol * 4;

    // main GEMM: [64,32] @ [32,256], packed f32x2
    #pragma unroll 4
    for (int k = 0; k < ED; k++) {
        u64 aa0 = pack2(sE[mg * 4 + 0][k], sE[mg * 4 + 0][k]);
        u64 aa1 = pack2(sE[mg * 4 + 1][k], sE[mg * 4 + 1][k]);
        u64 aa2 = pack2(sE[mg * 4 + 2][k], sE[mg * 4 + 2][k]);
        u64 aa3 = pack2(sE[mg * 4 + 3][k], sE[mg * 4 + 3][k]);
        u64 w[8];
        uint32_t a = sMb + k * (SD * 4);
        lds_v2u64(w[0], w[1], a);
        lds_v2u64(w[2], w[3], a + 16);
        lds_v2u64(w[4], w[5], a + 32);
        lds_v2u64(w[6], w[7], a + 48);
        #pragma unroll
        for (int u = 0; u < 8; u++) {
            acc2[0][u] = ffma2(aa0, w[u], acc2[0][u]);
            acc2[1][u] = ffma2(aa1, w[u], acc2[1][u]);
            acc2[2][u] = ffma2(aa2, w[u], acc2[2][u]);
            acc2[3][u] = ffma2(aa3, w[u], acc2[3][u]);
        }
    }

    // add G[i] + G[j] + d * W0[256,:]  (packed)
    u64 wd2[8];
    {
        const u64* wdp = (const u64*)(W0 + (size_t)SD * SD + ccol);
        #pragma unroll
        for (int u = 0; u < 8; u++) wd2[u] = wdp[u];
    }
    #pragma unroll
    for (int r = 0; r < 4; r++) {
        int m = mg * 4 + r;
        const u64* Gi = (const u64*)&g_G[sI[m] * SD + ccol];
        const u64* Gj = (const u64*)&g_G[sJ[m] * SD + ccol];
        float dm = sD[m];
        u64 dd = pack2(dm, dm);
        #pragma unroll
        for (int u = 0; u < 8; u++) {
            u64 v = ffma2(dd, wd2[u], acc2[r][u]);
            v = fadd2(v, Gi[u]);
            v = fadd2(v, Gj[u]);
            acc2[r][u] = v;
        }
    }

    // silu + second GEMM [*,256]@[256,5]; packed over row-pairs (0,1) and (2,3)
    u64 pb01[NBT], pb23[NBT];
    #pragma unroll
    for (int b = 0; b < NBT; b++) { pb01[b] = 0ull; pb23[b] = 0ull; }

    #pragma unroll
    for (int u = 0; u < 8; u++) {
        float z00, z01, z10, z11, z20, z21, z30, z31;
        unpack2(acc2[0][u], z00, z01);
        unpack2(acc2[1][u], z10, z11);
        unpack2(acc2[2][u], z20, z21);
        unpack2(acc2[3][u], z30, z31);
        float h[2][4] = {
            { silu_f(z00), silu_f(z10), silu_f(z20), silu_f(z30) },
            { silu_f(z01), silu_f(z11), silu_f(z21), silu_f(z31) } };
        #pragma unroll
        for (int s = 0; s < 2; s++) {
            int cc = ccol + 2 * u + s;
            u64 h01 = pack2(h[s][0], h[s][1]);
            u64 h23 = pack2(h[s][2], h[s][3]);
            #pragma unroll
            for (int b = 0; b < NBT; b++) {
                float w = __ldg(&W1[cc * NBT + b]);
                u64 ww = pack2(w, w);
                pb01[b] = ffma2(h01, ww, pb01[b]);
                pb23[b] = ffma2(h23, ww, pb23[b]);
            }
        }
    }

    // reduce over the 16 column-groups (16-lane shuffle segments)
    for (int off = 8; off >= 1; off >>= 1) {
        #pragma unroll
        for (int b = 0; b < NBT; b++) {
            pb01[b] = fadd2(pb01[b], __shfl_down_sync(0xffffffffu, pb01[b], off, 16));
            pb23[b] = fadd2(pb23[b], __shfl_down_sync(0xffffffffu, pb23[b], off, 16));
        }
    }
    if (ng == 0) {
        #pragma unroll
        for (int b = 0; b < NBT; b++) {
            float r0, r1, r2, r3;
            unpack2(pb01[b], r0, r1);
            unpack2(pb23[b], r2, r3);
            float bb1 = __ldg(&b1[b]);
            out_bonds[(base + mg * 4 + 0) * NBT + b] = r0 + bb1;
            out_bonds[(base + mg * 4 + 1) * NBT + b] = r1 + bb1;
            out_bonds[(base + mg * 4 + 2) * NBT + b] = r2 + bb1;
            out_bonds[(base + mg * 4 + 3) * NBT + b] = r3 + bb1;
        }
    }
}

extern "C" void kernel_launch(void* const* d_in, const int* in_sizes, int n_in,
                              void* d_out, int out_size)
{
    const float* s     = (const float*)d_in[0];
    const float* v     = (const float*)d_in[1];
    const float* p     = (const float*)d_in[2];
    const float* e     = (const float*)d_in[3];
    const int*   batch = (const int*)  d_in[4];
    const int*   eg    = (const int*)  d_in[5];
    const float* Ws    = (const float*)d_in[6];
    const float* bs    = (const float*)d_in[7];
    const float* Wc    = (const float*)d_in[8];
    const float* Wa    = (const float*)d_in[9];
    const float* ba    = (const float*)d_in[10];
    const float* Wb    = (const float*)d_in[11];
    const float* bb    = (const float*)d_in[12];
    const float* W0    = (const float*)d_in[13];
    const float* b0    = (const float*)d_in[14];
    const float* W1    = (const float*)d_in[15];
    const float* b1    = (const float*)d_in[16];

    float* out        = (float*)d_out;
    float* out_coords = out;                         // [2048, 3]
    float* out_atoms  = out + NN * 3;                // [2048, 16]
    float* out_bonds  = out + NN * 3 + NN * NAF;     // [262144, 5]

    k_clear  <<<2048, 256>>>();
    k_scatter<<<EE / 256, 256>>>(eg);
    k_node1  <<<NN / 8, 256>>>(s, v, p, Ws, bs, Wc);
    k_mw     <<<ED + 1, 1024>>>(Wb, bb, W0, b0);
    k_molmean<<<NMOL, 128>>>(batch);
    k_center <<<NN / 256, 256>>>(batch, out_coords);
    k_node2  <<<NN / 8, 256>>>(W0, Wa, ba, out_atoms);
    k_edge   <<<EE / 64, 256>>>(eg, e, W0, W1, b1, out_bonds);
}

// round 3
// speedup vs baseline: 3.5708x; 3.5708x over previous
#include <cuda_runtime.h>
#include <cstdint>

#define NN   2048
#define EE   262144
#define SD   256
#define VD   64
#define ED   32
#define NMOL 64
#define NAF  16
#define NBT  5

// ---- scratch (device globals; no allocations) ----
__device__ __align__(16) float g_sh[NN * SD];        // s_h = silu(s@Ws+bs)
__device__ __align__(16) float g_G[NN * SD];         // G = s_h @ W0[0:256,:]
__device__ __align__(16) float g_cpraw[NN * 3];      // p + v@Wc
__device__ __align__(16) float g_cp[NN * 3];         // centered coords
__device__ __align__(16) float g_molmean[NMOL * 3];
__device__ __align__(16) float g_M[ED * SD];         // M = Wb @ W0a
__device__ __align__(16) float g_c0[SD];             // c0 = b0 + bb @ W0a
__device__ int   g_map[NN * NN];                     // last-edge-index map

__device__ __forceinline__ float silu_f(float x) {
    return __fdividef(x, 1.0f + __expf(-x));
}

// ---- K0: clear map ----
__global__ void k_clear() {
    int i = blockIdx.x * blockDim.x + threadIdx.x;
    int stride = gridDim.x * blockDim.x;
    for (; i < NN * NN; i += stride) g_map[i] = -1;
}

// ---- K5: scatter last-edge-wins (atomicMax over edge idx == sequential last write) ----
__global__ void k_scatter(const int* __restrict__ eg) {
    int k = blockIdx.x * blockDim.x + threadIdx.x;
    if (k < EE) {
        int j = eg[k];
        int i = eg[EE + k];
        atomicMax(&g_map[j * NN + i], k);
    }
}

// ---- K1: s_h = silu(s@Ws+bs), cpraw = p + v@Wc ----
__global__ __launch_bounds__(256) void k_node1(
    const float* __restrict__ s, const float* __restrict__ v,
    const float* __restrict__ p, const float* __restrict__ Ws,
    const float* __restrict__ bs, const float* __restrict__ Wc)
{
    __shared__ float ss[8][SD];
    const int t = threadIdx.x;
    const int n0 = blockIdx.x * 8;
    #pragma unroll
    for (int r = 0; r < 8; r++) ss[r][t] = s[(n0 + r) * SD + t];
    __syncthreads();

    float acc[8];
    #pragma unroll
    for (int r = 0; r < 8; r++) acc[r] = 0.0f;

    for (int k = 0; k < SD; k += 4) {
        float w0 = Ws[(k + 0) * SD + t];
        float w1 = Ws[(k + 1) * SD + t];
        float w2 = Ws[(k + 2) * SD + t];
        float w3 = Ws[(k + 3) * SD + t];
        #pragma unroll
        for (int r = 0; r < 8; r++) {
            float4 a = *(const float4*)&ss[r][k];
            acc[r] += a.x * w0;
            acc[r] += a.y * w1;
            acc[r] += a.z * w2;
            acc[r] += a.w * w3;
        }
    }
    float b = bs[t];
    #pragma unroll
    for (int r = 0; r < 8; r++) {
        g_sh[(n0 + r) * SD + t] = silu_f(acc[r] + b);
    }

    if (t < 24) {
        int r = t / 3, x = t % 3;
        const float* vp = &v[(n0 + r) * 3 * VD + x * VD];
        float sum = 0.0f;
        #pragma unroll 8
        for (int q = 0; q < VD; q++) sum += vp[q] * Wc[q];
        g_cpraw[(n0 + r) * 3 + x] = p[(n0 + r) * 3 + x] + sum;
    }
}

// ---- K2: M = Wb@W0a (blocks 0..31), c0 = b0 + bb@W0a (block 32); split-K x4 ----
__global__ __launch_bounds__(1024) void k_mw(
    const float* __restrict__ Wb, const float* __restrict__ bb,
    const float* __restrict__ W0, const float* __restrict__ b0)
{
    __shared__ float row[SD];
    __shared__ float part[3][SD];
    const int t = threadIdx.x;
    const int c = t & 255;
    const int pz = t >> 8;
    const int q = blockIdx.x;
    if (t < SD) row[t] = (q < ED) ? Wb[q * SD + t] : bb[t];
    __syncthreads();

    float acc = 0.0f;
    const int k0 = pz * 64;
    #pragma unroll 4
    for (int k = k0; k < k0 + 64; k += 4) {
        float4 a = *(const float4*)&row[k];
        acc += a.x * W0[(k + 0) * SD + c];
        acc += a.y * W0[(k + 1) * SD + c];
        acc += a.z * W0[(k + 2) * SD + c];
        acc += a.w * W0[(k + 3) * SD + c];
    }
    if (pz > 0) part[pz - 1][c] = acc;
    __syncthreads();
    if (pz == 0) {
        float tot = acc + part[0][c] + part[1][c] + part[2][c];
        if (q < ED) g_M[q * SD + c] = tot;
        else        g_c0[c] = b0[c] + tot;
    }
}

// ---- K3a: per-mol mean ----
__global__ void k_molmean(const int* __restrict__ batch) {
    __shared__ float red[128][4];
    const int b = blockIdx.x;
    const int t = threadIdx.x;
    float sx = 0.f, sy = 0.f, sz = 0.f, c = 0.f;
    for (int n = t; n < NN; n += 128) {
        if (batch[n] == b) {
            sx += g_cpraw[n * 3 + 0];
            sy += g_cpraw[n * 3 + 1];
            sz += g_cpraw[n * 3 + 2];
            c  += 1.0f;
        }
    }
    red[t][0] = sx; red[t][1] = sy; red[t][2] = sz; red[t][3] = c;
    __syncthreads();
    for (int s = 64; s > 0; s >>= 1) {
        if (t < s) {
            red[t][0] += red[t + s][0];
            red[t][1] += red[t + s][1];
            red[t][2] += red[t + s][2];
            red[t][3] += red[t + s][3];
        }
        __syncthreads();
    }
    if (t < 3) g_molmean[b * 3 + t] = red[0][t] / fmaxf(red[0][3], 1.0f);
}

// ---- K3b: center coords + write output ----
__global__ void k_center(const int* __restrict__ batch, float* __restrict__ out_coords) {
    int n = blockIdx.x * blockDim.x + threadIdx.x;
    if (n < NN) {
        int b = batch[n];
        #pragma unroll
        for (int x = 0; x < 3; x++) {
            float cpv = g_cpraw[n * 3 + x] - g_molmean[b * 3 + x];
            g_cp[n * 3 + x] = cpv;
            out_coords[n * 3 + x] = cpv;
        }
    }
}

// ---- K4: G = s_h@W0a and atoms_pred = s_h@Wa + ba ----
__global__ __launch_bounds__(256) void k_node2(
    const float* __restrict__ W0, const float* __restrict__ Wa,
    const float* __restrict__ ba, float* __restrict__ out_atoms)
{
    __shared__ float sh[8][SD];
    const int t = threadIdx.x;
    const int n0 = blockIdx.x * 8;
    #pragma unroll
    for (int r = 0; r < 8; r++) sh[r][t] = g_sh[(n0 + r) * SD + t];
    __syncthreads();

    float acc[8];
    #pragma unroll
    for (int r = 0; r < 8; r++) acc[r] = 0.0f;
    for (int k = 0; k < SD; k += 4) {
        float w0 = W0[(k + 0) * SD + t];
        float w1 = W0[(k + 1) * SD + t];
        float w2 = W0[(k + 2) * SD + t];
        float w3 = W0[(k + 3) * SD + t];
        #pragma unroll
        for (int r = 0; r < 8; r++) {
            float4 a = *(const float4*)&sh[r][k];
            acc[r] += a.x * w0;
            acc[r] += a.y * w1;
            acc[r] += a.z * w2;
            acc[r] += a.w * w3;
        }
    }
    #pragma unroll
    for (int r = 0; r < 8; r++) g_G[(n0 + r) * SD + t] = acc[r];

    if (t < 8 * NAF) {
        int r = t >> 4, a = t & 15;
        float sum = 0.0f;
        for (int k = 0; k < SD; k++) sum += sh[r][k] * Wa[k * NAF + a];
        out_atoms[(n0 + r) * NAF + a] = sum + ba[a];
    }
}

// ---- K6: fused edge kernel, conflict-free warp layout ----
// Warp = 8 edges x 32 col-lanes; lane owns cols {lane*4..+3, 128+lane*4..+3}.
// z = c0 + e_sym@M + G[i] + G[j] + d*W0[256,:];  bonds = silu(z)@W1 + b1
__global__ __launch_bounds__(256, 2) void k_edge(
    const int* __restrict__ eg, const float* __restrict__ efeat,
    const float* __restrict__ W0, const float* __restrict__ W1,
    const float* __restrict__ b1, float* __restrict__ out_bonds)
{
    __shared__ float sM[ED][SD];       // 32 KB
    __shared__ float sE[64][ED + 1];   // 8.25 KB
    __shared__ int   sI[64], sJ[64], sKa[64], sKb[64];
    __shared__ float sD[64];

    const int t    = threadIdx.x;
    const int lane = t & 31;
    const int w    = t >> 5;           // warp 0..7
    const int e0   = w * 8;            // local first edge of this warp
    const int base = blockIdx.x * 64;

    {   // stage M into smem (2048 float4)
        const float4* src = (const float4*)g_M;
        float4* dst = (float4*)sM;
        #pragma unroll
        for (int r = 0; r < 8; r++) dst[t + 256 * r] = src[t + 256 * r];
    }
    if (t < 64) {
        int eid = base + t;
        int j = eg[eid], i = eg[EE + eid];
        sI[t] = i; sJ[t] = j;
        sKa[t] = g_map[j * NN + i];
        sKb[t] = g_map[i * NN + j];
        float dx = g_cp[i * 3 + 0] - g_cp[j * 3 + 0];
        float dy = g_cp[i * 3 + 1] - g_cp[j * 3 + 1];
        float dz = g_cp[i * 3 + 2] - g_cp[j * 3 + 2];
        sD[t] = dx * dx + dy * dy + dz * dz;
    }
    __syncthreads();

    // build e_sym = 0.5*(e[ka] + (kb>=0 ? e[kb] : 0))
    #pragma unroll
    for (int r = 0; r < 8; r++) {
        int idx = t + 256 * r;
        int m = idx >> 5, q = idx & 31;
        int ka = sKa[m], kb = sKb[m];
        float vv = efeat[ka * ED + q];
        if (kb >= 0) vv += efeat[kb * ED + q];
        sE[m][q] = 0.5f * vv;
    }
    __syncthreads();

    const int cA = lane * 4;           // cols cA..cA+3
    const int cB = 128 + lane * 4;     // cols cB..cB+3

    // acc[r][0..3] = cols cA.., acc[r][4..7] = cols cB..
    float acc[8][8];
    {
        float4 a0 = *(const float4*)&g_c0[cA];
        float4 b0v = *(const float4*)&g_c0[cB];
        #pragma unroll
        for (int r = 0; r < 8; r++) {
            acc[r][0] = a0.x;  acc[r][1] = a0.y;  acc[r][2] = a0.z;  acc[r][3] = a0.w;
            acc[r][4] = b0v.x; acc[r][5] = b0v.y; acc[r][6] = b0v.z; acc[r][7] = b0v.w;
        }
    }

    // main GEMM: per k, two conflict-free LDS.128 + 8 broadcast sE + 64 FFMA
    #pragma unroll 4
    for (int k = 0; k < ED; k++) {
        float4 mA = *(const float4*)&sM[k][cA];
        float4 mB = *(const float4*)&sM[k][cB];
        #pragma unroll
        for (int r = 0; r < 8; r++) {
            float a = sE[e0 + r][k];
            acc[r][0] += a * mA.x;
            acc[r][1] += a * mA.y;
            acc[r][2] += a * mA.z;
            acc[r][3] += a * mA.w;
            acc[r][4] += a * mB.x;
            acc[r][5] += a * mB.y;
            acc[r][6] += a * mB.z;
            acc[r][7] += a * mB.w;
        }
    }

    // add G[i] + G[j] + d * W0[256,:]
    {
        const float4* wdp = (const float4*)(W0 + (size_t)SD * SD);
        float4 wA = wdp[lane];
        float4 wB = wdp[32 + lane];
        #pragma unroll
        for (int r = 0; r < 8; r++) {
            int m = e0 + r;
            const float* Gi = &g_G[sI[m] * SD];
            const float* Gj = &g_G[sJ[m] * SD];
            float4 giA = *(const float4*)&Gi[cA];
            float4 gjA = *(const float4*)&Gj[cA];
            float4 giB = *(const float4*)&Gi[cB];
            float4 gjB = *(const float4*)&Gj[cB];
            float dm = sD[m];
            acc[r][0] += giA.x + gjA.x + dm * wA.x;
            acc[r][1] += giA.y + gjA.y + dm * wA.y;
            acc[r][2] += giA.z + gjA.z + dm * wA.z;
            acc[r][3] += giA.w + gjA.w + dm * wA.w;
            acc[r][4] += giB.x + gjB.x + dm * wB.x;
            acc[r][5] += giB.y + gjB.y + dm * wB.y;
            acc[r][6] += giB.z + gjB.z + dm * wB.z;
            acc[r][7] += giB.w + gjB.w + dm * wB.w;
        }
    }

    // silu + second GEMM [*,256]@[256,5]; two passes of 4 edges to cap registers
    #pragma unroll
    for (int half = 0; half < 2; half++) {
        float pb[4][NBT];
        #pragma unroll
        for (int r = 0; r < 4; r++)
            #pragma unroll
            for (int b = 0; b < NBT; b++) pb[r][b] = 0.0f;

        #pragma unroll
        for (int u = 0; u < 8; u++) {
            int cc = (u < 4) ? (cA + u) : (cB + u - 4);
            float w1r[NBT];
            #pragma unroll
            for (int b = 0; b < NBT; b++) w1r[b] = __ldg(&W1[cc * NBT + b]);
            #pragma unroll
            for (int r = 0; r < 4; r++) {
                float h = silu_f(acc[half * 4 + r][u]);
                #pragma unroll
                for (int b = 0; b < NBT; b++) pb[r][b] += h * w1r[b];
            }
        }

        // full-warp reduce (cols are spread over all 32 lanes)
        #pragma unroll
        for (int off = 16; off >= 1; off >>= 1) {
            #pragma unroll
            for (int r = 0; r < 4; r++)
                #pragma unroll
                for (int b = 0; b < NBT; b++)
                    pb[r][b] += __shfl_down_sync(0xffffffffu, pb[r][b], off);
        }
        if (lane == 0) {
            #pragma unroll
            for (int r = 0; r < 4; r++) {
                int eid = base + e0 + half * 4 + r;
                #pragma unroll
                for (int b = 0; b < NBT; b++)
                    out_bonds[eid * NBT + b] = pb[r][b] + __ldg(&b1[b]);
            }
        }
    }
}

extern "C" void kernel_launch(void* const* d_in, const int* in_sizes, int n_in,
                              void* d_out, int out_size)
{
    const float* s     = (const float*)d_in[0];
    const float* v     = (const float*)d_in[1];
    const float* p     = (const float*)d_in[2];
    const float* e     = (const float*)d_in[3];
    const int*   batch = (const int*)  d_in[4];
    const int*   eg    = (const int*)  d_in[5];
    const float* Ws    = (const float*)d_in[6];
    const float* bs    = (const float*)d_in[7];
    const float* Wc    = (const float*)d_in[8];
    const float* Wa    = (const float*)d_in[9];
    const float* ba    = (const float*)d_in[10];
    const float* Wb    = (const float*)d_in[11];
    const float* bb    = (const float*)d_in[12];
    const float* W0    = (const float*)d_in[13];
    const float* b0    = (const float*)d_in[14];
    const float* W1    = (const float*)d_in[15];
    const float* b1    = (const float*)d_in[16];

    float* out        = (float*)d_out;
    float* out_coords = out;                         // [2048, 3]
    float* out_atoms  = out + NN * 3;                // [2048, 16]
    float* out_bonds  = out + NN * 3 + NN * NAF;     // [262144, 5]

    k_clear  <<<2048, 256>>>();
    k_scatter<<<EE / 256, 256>>>(eg);
    k_node1  <<<NN / 8, 256>>>(s, v, p, Ws, bs, Wc);
    k_mw     <<<ED + 1, 1024>>>(Wb, bb, W0, b0);
    k_molmean<<<NMOL, 128>>>(batch);
    k_center <<<NN / 256, 256>>>(batch, out_coords);
    k_node2  <<<NN / 8, 256>>>(W0, Wa, ba, out_atoms);
    k_edge   <<<EE / 64, 256>>>(eg, e, W0, W1, b1, out_bonds);
}

// round 7
// speedup vs baseline: 4.8340x; 1.3538x over previous
#include <cuda_runtime.h>
#include <cstdint>

#define NN   2048
#define EE   262144
#define SD   256
#define VD   64
#define ED   32
#define NMOL 64
#define NAF  16
#define NBT  5
#define EPC  64            // edges per CTA in k_edge

// ---- scratch (device globals; no allocations) ----
__device__ __align__(16) float g_G[NN * SD];         // G = s_h @ W0[0:256,:] (fp32)
__device__ __align__(16) float g_cpraw[NN * 3];
__device__ __align__(16) float g_cp[NN * 3];
__device__ __align__(16) float g_molmean[NMOL * 3];
__device__ __align__(16) float g_M[ED * SD];         // M = Wb@W0a, tf32-rounded bits
__device__ __align__(16) float g_c0[SD];             // c0 = b0 + bb @ W0a (fp32)
__device__ int   g_map[NN * NN];

__device__ __forceinline__ float silu_f(float x) {
    return __fdividef(x, 1.0f + __expf(-x));
}

__device__ __forceinline__ uint32_t f2tf32(float x) {
    uint32_t r;
    asm("cvt.rna.tf32.f32 %0, %1;" : "=r"(r) : "f"(x));
    return r;
}

// m16n8k8 tf32 mma: D += A@B  (A row-major, B col-major)
__device__ __forceinline__ void mma_tf32(float* c, const uint32_t* a,
                                         uint32_t b0, uint32_t b1) {
    asm volatile(
        "mma.sync.aligned.m16n8k8.row.col.f32.tf32.tf32.f32 "
        "{%0,%1,%2,%3}, {%4,%5,%6,%7}, {%8,%9}, {%0,%1,%2,%3};\n"
        : "+f"(c[0]), "+f"(c[1]), "+f"(c[2]), "+f"(c[3])
        : "r"(a[0]), "r"(a[1]), "r"(a[2]), "r"(a[3]), "r"(b0), "r"(b1));
}

// ---- K0: clear map ----
__global__ void k_clear() {
    int i = blockIdx.x * blockDim.x + threadIdx.x;
    int stride = gridDim.x * blockDim.x;
    for (; i < NN * NN; i += stride) g_map[i] = -1;
}

// ---- K5: scatter last-edge-wins ----
__global__ void k_scatter(const int* __restrict__ eg) {
    int k = blockIdx.x * blockDim.x + threadIdx.x;
    if (k < EE) {
        int j = eg[k];
        int i = eg[EE + k];
        atomicMax(&g_map[j * NN + i], k);
    }
}

// ---- K1: fused node kernel: s_h (smem only) -> G, atoms, coords ----
__global__ __launch_bounds__(256) void k_node(
    const float* __restrict__ s, const float* __restrict__ v,
    const float* __restrict__ p, const float* __restrict__ Ws,
    const float* __restrict__ bs, const float* __restrict__ Wc,
    const float* __restrict__ W0, const float* __restrict__ Wa,
    const float* __restrict__ ba, float* __restrict__ out_atoms)
{
    __shared__ float ss[8][SD];
    __shared__ float sh[8][SD];
    const int t = threadIdx.x;
    const int n0 = blockIdx.x * 8;
    #pragma unroll
    for (int r = 0; r < 8; r++) ss[r][t] = s[(n0 + r) * SD + t];
    __syncthreads();

    float acc[8];
    #pragma unroll
    for (int r = 0; r < 8; r++) acc[r] = 0.0f;
    for (int k = 0; k < SD; k += 4) {
        float w0 = Ws[(k + 0) * SD + t];
        float w1 = Ws[(k + 1) * SD + t];
        float w2 = Ws[(k + 2) * SD + t];
        float w3 = Ws[(k + 3) * SD + t];
        #pragma unroll
        for (int r = 0; r < 8; r++) {
            float4 a = *(const float4*)&ss[r][k];
            acc[r] += a.x * w0;
            acc[r] += a.y * w1;
            acc[r] += a.z * w2;
            acc[r] += a.w * w3;
        }
    }
    float b = bs[t];
    #pragma unroll
    for (int r = 0; r < 8; r++) sh[r][t] = silu_f(acc[r] + b);

    if (t < 24) {
        int r = t / 3, x = t % 3;
        const float* vp = &v[(n0 + r) * 3 * VD + x * VD];
        float sum = 0.0f;
        #pragma unroll 8
        for (int q = 0; q < VD; q++) sum += vp[q] * Wc[q];
        g_cpraw[(n0 + r) * 3 + x] = p[(n0 + r) * 3 + x] + sum;
    }
    __syncthreads();

    #pragma unroll
    for (int r = 0; r < 8; r++) acc[r] = 0.0f;
    for (int k = 0; k < SD; k += 4) {
        float w0 = W0[(k + 0) * SD + t];
        float w1 = W0[(k + 1) * SD + t];
        float w2 = W0[(k + 2) * SD + t];
        float w3 = W0[(k + 3) * SD + t];
        #pragma unroll
        for (int r = 0; r < 8; r++) {
            float4 a = *(const float4*)&sh[r][k];
            acc[r] += a.x * w0;
            acc[r] += a.y * w1;
            acc[r] += a.z * w2;
            acc[r] += a.w * w3;
        }
    }
    #pragma unroll
    for (int r = 0; r < 8; r++) g_G[(n0 + r) * SD + t] = acc[r];

    if (t < 8 * NAF) {
        int r = t >> 4, a = t & 15;
        float sum = 0.0f;
        for (int k = 0; k < SD; k++) sum += sh[r][k] * Wa[k * NAF + a];
        out_atoms[(n0 + r) * NAF + a] = sum + ba[a];
    }
}

// ---- K2: g_M[k][n] = (Wb@W0a)[k][n] tf32-rounded; c0 = b0 + bb@W0a ----
__global__ __launch_bounds__(1024) void k_mw(
    const float* __restrict__ Wb, const float* __restrict__ bb,
    const float* __restrict__ W0, const float* __restrict__ b0)
{
    __shared__ float row[SD];
    __shared__ float part[3][SD];
    const int t = threadIdx.x;
    const int c = t & 255;
    const int pz = t >> 8;
    const int q = blockIdx.x;
    if (t < SD) row[t] = (q < ED) ? Wb[q * SD + t] : bb[t];
    __syncthreads();

    float acc = 0.0f;
    const int k0 = pz * 64;
    #pragma unroll 4
    for (int k = k0; k < k0 + 64; k += 4) {
        float4 a = *(const float4*)&row[k];
        acc += a.x * W0[(k + 0) * SD + c];
        acc += a.y * W0[(k + 1) * SD + c];
        acc += a.z * W0[(k + 2) * SD + c];
        acc += a.w * W0[(k + 3) * SD + c];
    }
    if (pz > 0) part[pz - 1][c] = acc;
    __syncthreads();
    if (pz == 0) {
        float tot = acc + part[0][c] + part[1][c] + part[2][c];
        if (q < ED) g_M[q * SD + c] = __uint_as_float(f2tf32(tot));
        else        g_c0[c] = b0[c] + tot;
    }
}

// ---- K3a: per-mol mean ----
__global__ void k_molmean(const int* __restrict__ batch) {
    __shared__ float red[128][4];
    const int b = blockIdx.x;
    const int t = threadIdx.x;
    float sx = 0.f, sy = 0.f, sz = 0.f, c = 0.f;
    for (int n = t; n < NN; n += 128) {
        if (batch[n] == b) {
            sx += g_cpraw[n * 3 + 0];
            sy += g_cpraw[n * 3 + 1];
            sz += g_cpraw[n * 3 + 2];
            c  += 1.0f;
        }
    }
    red[t][0] = sx; red[t][1] = sy; red[t][2] = sz; red[t][3] = c;
    __syncthreads();
    for (int s = 64; s > 0; s >>= 1) {
        if (t < s) {
            red[t][0] += red[t + s][0];
            red[t][1] += red[t + s][1];
            red[t][2] += red[t + s][2];
            red[t][3] += red[t + s][3];
        }
        __syncthreads();
    }
    if (t < 3) g_molmean[b * 3 + t] = red[0][t] / fmaxf(red[0][3], 1.0f);
}

// ---- K3b: center coords + write output ----
__global__ void k_center(const int* __restrict__ batch, float* __restrict__ out_coords) {
    int n = blockIdx.x * blockDim.x + threadIdx.x;
    if (n < NN) {
        int b = batch[n];
        #pragma unroll
        for (int x = 0; x < 3; x++) {
            float cpv = g_cpraw[n * 3 + x] - g_molmean[b * 3 + x];
            g_cp[n * 3 + x] = cpv;
            out_coords[n * 3 + x] = cpv;
        }
    }
}

// ---- K6: mma.sync tf32 edge kernel. 64 edges/CTA, 8 warps. ----
// smem layout (bytes)
#define BPAD 264                           // B row pad (floats): bank-perfect
#define APAD 36                            // A row pad (floats): bank-perfect
#define SM_B    0                          // [32][264] u32: 33792
#define SM_A    33792                      // [64][36]  u32: 9216
#define SM_W1   43008                      // [256][8]  f32: 8192
#define SM_C0   51200                      // 1024
#define SM_WD   52224                      // 1024
#define SM_DD   53248                      // 256
#define SM_II   53504                      // 256
#define SM_JJ   53760                      // 256
#define SM_KA   54016                      // 256
#define SM_KB   54272                      // 256
#define SM_TOTAL 54528

__global__ __launch_bounds__(256, 2) void k_edge(
    const int* __restrict__ eg, const float* __restrict__ efeat,
    const float* __restrict__ W0, const float* __restrict__ W1,
    const float* __restrict__ b1, float* __restrict__ out_bonds)
{
    extern __shared__ char smem[];
    uint32_t* sB  = (uint32_t*)(smem + SM_B);
    uint32_t* sA  = (uint32_t*)(smem + SM_A);
    float*    sW1 = (float*)(smem + SM_W1);
    float*    sC0 = (float*)(smem + SM_C0);
    float*    sWD = (float*)(smem + SM_WD);
    float*    sDD = (float*)(smem + SM_DD);
    int*      sII = (int*)  (smem + SM_II);
    int*      sJJ = (int*)  (smem + SM_JJ);
    int*      sKA = (int*)  (smem + SM_KA);
    int*      sKB = (int*)  (smem + SM_KB);

    const int t    = threadIdx.x;
    const int lane = t & 31;
    const int wid  = t >> 5;
    const int base = blockIdx.x * EPC;

    // ---- stage B [32][256] (tf32 bits) into padded smem: 2048 float4 ----
    {
        const float4* src = (const float4*)g_M;
        #pragma unroll
        for (int r = 0; r < 8; r++) {
            int idx = t + 256 * r;          // float4 index
            int k = idx >> 6, n4 = idx & 63;
            *(float4*)&sB[k * BPAD + n4 * 4] = src[idx];
        }
    }
    // ---- stage W1 (scalar loads — W1 rows are only 4B-aligned), c0, wd ----
    {
        sW1[t * 8 + 0] = W1[t * NBT + 0];
        sW1[t * 8 + 1] = W1[t * NBT + 1];
        sW1[t * 8 + 2] = W1[t * NBT + 2];
        sW1[t * 8 + 3] = W1[t * NBT + 3];
        sW1[t * 8 + 4] = W1[t * NBT + 4];
        sC0[t] = g_c0[t];
        sWD[t] = W0[(size_t)SD * SD + t];
    }
    // ---- edge meta ----
    if (t < EPC) {
        int eid = base + t;
        int j = eg[eid], i = eg[EE + eid];
        sII[t] = i; sJJ[t] = j;
        sKA[t] = g_map[j * NN + i];
        sKB[t] = g_map[i * NN + j];
        float dx = g_cp[i * 3 + 0] - g_cp[j * 3 + 0];
        float dy = g_cp[i * 3 + 1] - g_cp[j * 3 + 1];
        float dz = g_cp[i * 3 + 2] - g_cp[j * 3 + 2];
        sDD[t] = dx * dx + dy * dy + dz * dz;
    }
    __syncthreads();

    // ---- build A = e_sym [64][32] tf32, padded ----
    {
        int m = t >> 2;                    // edge 0..63
        int qd = t & 3;                    // feature quad: cols qd*8..+7
        int ka = sKA[m], kb = sKB[m];
        const float4* ea = (const float4*)&efeat[ka * ED + qd * 8];
        float4 v0 = ea[0], v1 = ea[1];
        if (kb >= 0) {
            const float4* ebp = (const float4*)&efeat[kb * ED + qd * 8];
            float4 w0 = ebp[0], w1 = ebp[1];
            v0.x += w0.x; v0.y += w0.y; v0.z += w0.z; v0.w += w0.w;
            v1.x += w1.x; v1.y += w1.y; v1.z += w1.z; v1.w += w1.w;
        }
        uint32_t* dst = &sA[m * APAD + qd * 8];
        dst[0] = f2tf32(0.5f * v0.x); dst[1] = f2tf32(0.5f * v0.y);
        dst[2] = f2tf32(0.5f * v0.z); dst[3] = f2tf32(0.5f * v0.w);
        dst[4] = f2tf32(0.5f * v1.x); dst[5] = f2tf32(0.5f * v1.y);
        dst[6] = f2tf32(0.5f * v1.z); dst[7] = f2tf32(0.5f * v1.w);
    }
    __syncthreads();

    // ---- MMA: warp tile M32 x N64 x K32 ----
    const int g  = lane >> 2;             // 0..7
    const int tg = lane & 3;              // 0..3
    const int wm = wid >> 2;              // 0..1 -> edges wm*32..
    const int wn = wid & 3;               // 0..3 -> cols wn*64..

    float acc[2][8][4];
    #pragma unroll
    for (int mf = 0; mf < 2; mf++)
        #pragma unroll
        for (int nf = 0; nf < 8; nf++)
            #pragma unroll
            for (int x = 0; x < 4; x++) acc[mf][nf][x] = 0.0f;

    #pragma unroll
    for (int ks = 0; ks < 4; ks++) {
        uint32_t a[2][4];
        #pragma unroll
        for (int mf = 0; mf < 2; mf++) {
            int r0 = wm * 32 + mf * 16 + g;
            a[mf][0] = sA[(r0 + 0) * APAD + ks * 8 + tg];
            a[mf][1] = sA[(r0 + 8) * APAD + ks * 8 + tg];
            a[mf][2] = sA[(r0 + 0) * APAD + ks * 8 + tg + 4];
            a[mf][3] = sA[(r0 + 8) * APAD + ks * 8 + tg + 4];
        }
        #pragma unroll
        for (int nf = 0; nf < 8; nf++) {
            int cc = wn * 64 + nf * 8 + g;
            uint32_t b0 = sB[(ks * 8 + tg + 0) * BPAD + cc];
            uint32_t b1 = sB[(ks * 8 + tg + 4) * BPAD + cc];
            mma_tf32(acc[0][nf], a[0], b0, b1);
            mma_tf32(acc[1][nf], a[1], b0, b1);
        }
    }

    // ---- epilogue: z = acc + c0 + G[i]+G[j] + d*wd; silu; @W1 ----
    float pb[4][NBT];                      // 4 edge-rows per thread
    #pragma unroll
    for (int r = 0; r < 4; r++)
        #pragma unroll
        for (int b = 0; b < NBT; b++) pb[r][b] = 0.0f;

    #pragma unroll
    for (int mf = 0; mf < 2; mf++) {
        #pragma unroll
        for (int h = 0; h < 2; h++) {
            int m = wm * 32 + mf * 16 + g + h * 8;   // local edge
            const float* Gi = &g_G[sII[m] * SD];
            const float* Gj = &g_G[sJJ[m] * SD];
            float dm = sDD[m];
            int r = mf * 2 + h;
            #pragma unroll
            for (int nf = 0; nf < 8; nf++) {
                int col = wn * 64 + nf * 8 + 2 * tg;
                float2 gi = *(const float2*)&Gi[col];
                float2 gj = *(const float2*)&Gj[col];
                float z0 = acc[mf][nf][h * 2 + 0] + sC0[col + 0]
                         + gi.x + gj.x + dm * sWD[col + 0];
                float z1 = acc[mf][nf][h * 2 + 1] + sC0[col + 1]
                         + gi.y + gj.y + dm * sWD[col + 1];
                float h0 = silu_f(z0);
                float h1 = silu_f(z1);
                float4 wa = *(const float4*)&sW1[(col + 0) * 8];
                float  wae = sW1[(col + 0) * 8 + 4];
                float4 wb = *(const float4*)&sW1[(col + 1) * 8];
                float  wbe = sW1[(col + 1) * 8 + 4];
                pb[r][0] += h0 * wa.x + h1 * wb.x;
                pb[r][1] += h0 * wa.y + h1 * wb.y;
                pb[r][2] += h0 * wa.z + h1 * wb.z;
                pb[r][3] += h0 * wa.w + h1 * wb.w;
                pb[r][4] += h0 * wae  + h1 * wbe;
            }
        }
    }

    // reduce across the 4 lanes of each quad (same rows, different cols)
    #pragma unroll
    for (int off = 2; off >= 1; off >>= 1)
        #pragma unroll
        for (int r = 0; r < 4; r++)
            #pragma unroll
            for (int b = 0; b < NBT; b++)
                pb[r][b] += __shfl_down_sync(0xffffffffu, pb[r][b], off, 4);

    // combine partial sums across the 4 wn column-groups via smem
    __shared__ float sRed[4][EPC][NBT + 1];
    if (tg == 0) {
        #pragma unroll
        for (int r = 0; r < 4; r++) {
            int m = wm * 32 + (r >> 1) * 16 + g + (r & 1) * 8;
            #pragma unroll
            for (int b = 0; b < NBT; b++) sRed[wn][m][b] = pb[r][b];
        }
    }
    __syncthreads();
    for (int idx = t; idx < EPC * NBT; idx += 256) {
        int m = idx / NBT, b = idx % NBT;
        float sum = sRed[0][m][b] + sRed[1][m][b] + sRed[2][m][b] + sRed[3][m][b];
        out_bonds[(base + m) * NBT + b] = sum + __ldg(&b1[b]);
    }
}

extern "C" void kernel_launch(void* const* d_in, const int* in_sizes, int n_in,
                              void* d_out, int out_size)
{
    const float* s     = (const float*)d_in[0];
    const float* v     = (const float*)d_in[1];
    const float* p     = (const float*)d_in[2];
    const float* e     = (const float*)d_in[3];
    const int*   batch = (const int*)  d_in[4];
    const int*   eg    = (const int*)  d_in[5];
    const float* Ws    = (const float*)d_in[6];
    const float* bs    = (const float*)d_in[7];
    const float* Wc    = (const float*)d_in[8];
    const float* Wa    = (const float*)d_in[9];
    const float* ba    = (const float*)d_in[10];
    const float* Wb    = (const float*)d_in[11];
    const float* bb    = (const float*)d_in[12];
    const float* W0    = (const float*)d_in[13];
    const float* b0    = (const float*)d_in[14];
    const float* W1    = (const float*)d_in[15];
    const float* b1    = (const float*)d_in[16];

    float* out        = (float*)d_out;
    float* out_coords = out;                         // [2048, 3]
    float* out_atoms  = out + NN * 3;                // [2048, 16]
    float* out_bonds  = out + NN * 3 + NN * NAF;     // [262144, 5]

    cudaFuncSetAttribute(k_edge, cudaFuncAttributeMaxDynamicSharedMemorySize, SM_TOTAL);

    k_clear  <<<2048, 256>>>();
    k_scatter<<<EE / 256, 256>>>(eg);
    k_node   <<<NN / 8, 256>>>(s, v, p, Ws, bs, Wc, W0, Wa, ba, out_atoms);
    k_mw     <<<ED + 1, 1024>>>(Wb, bb, W0, b0);
    k_molmean<<<NMOL, 128>>>(batch);
    k_center <<<NN / 256, 256>>>(batch, out_coords);
    k_edge   <<<EE / EPC, 256, SM_TOTAL>>>(eg, e, W0, W1, b1, out_bonds);
}